// round 1
// baseline (speedup 1.0000x reference)
#include <cuda_runtime.h>
#include <math.h>

// Problem constants
#define L_   2
#define P_   3
#define R_   512
#define A_   196
#define V_   9487
#define B_   256
#define BA_  (B_*A_)        // 50176
#define KC_  (2*L_*A_)      // 784 (all 4 calls' a2a rows concatenated)
#define G4_  (4*R_)         // 2048

// ---------------------------------------------------------------------------
// Static device scratch (allocation-free)
// ---------------------------------------------------------------------------
__device__ float gM[(size_t)BA_ * KC_];     // 50176 x 784  (~157 MB): v pre-bias-tanh for ALL 4 calls
__device__ float g_hh  [B_ * A_];
__device__ float g_att [B_ * R_];
__device__ float g_sums[P_ * B_ * G4_];
__device__ float g_xt  [B_ * R_];
__device__ float g_nh  [B_ * R_];

// ---------------------------------------------------------------------------
// Generic NT GEMM: C[m,n] = sum_k A[m,k] * B[n,k] (+ bias[n]) (+= if accumulate)
// A: [M,K] row-major, B: [N,K] row-major (K-major both sides).
// Batched over grid.z with element strides sA/sB/sC/sBias (0 = broadcast).
// Tile 128x64x16, 256 threads, 8x4 micro-tile.
// ---------------------------------------------------------------------------
#define BM 128
#define BN 64
#define BK 16

__global__ __launch_bounds__(256)
void gemm_nt(const float* __restrict__ A, const float* __restrict__ Bm,
             float* __restrict__ C, const float* __restrict__ bias,
             int M, int N, int K,
             long long sA, long long sB, long long sC, long long sBias,
             int accumulate)
{
    const float* Ab = A  + (long long)blockIdx.z * sA;
    const float* Bb = Bm + (long long)blockIdx.z * sB;
    float*       Cb = C  + (long long)blockIdx.z * sC;
    const float* biasb = bias ? (bias + (long long)blockIdx.z * sBias) : nullptr;

    __shared__ float As[BK][BM];
    __shared__ float Bs[BK][BN];

    const int tid = threadIdx.x;
    const int tm  = tid >> 4;    // 0..15
    const int tn  = tid & 15;    // 0..15
    const int row0 = blockIdx.y * BM;
    const int col0 = blockIdx.x * BN;

    float acc[8][4];
    #pragma unroll
    for (int i = 0; i < 8; i++)
        #pragma unroll
        for (int j = 0; j < 4; j++) acc[i][j] = 0.f;

    for (int kb = 0; kb < K; kb += BK) {
        // load A tile: 128x16 = 512 float4, 2 per thread; store transposed As[k][m]
        #pragma unroll
        for (int l = 0; l < 2; l++) {
            int idx = tid + l * 256;         // 0..511
            int ml  = idx >> 2;              // 0..127
            int k4  = (idx & 3) << 2;        // 0,4,8,12
            float4 v = make_float4(0.f, 0.f, 0.f, 0.f);
            int gm = row0 + ml;
            if (gm < M)
                v = *reinterpret_cast<const float4*>(Ab + (long long)gm * K + kb + k4);
            As[k4 + 0][ml] = v.x;
            As[k4 + 1][ml] = v.y;
            As[k4 + 2][ml] = v.z;
            As[k4 + 3][ml] = v.w;
        }
        // load B tile: 64x16 = 256 float4, 1 per thread
        {
            int nl = tid >> 2;
            int k4 = (tid & 3) << 2;
            float4 v = make_float4(0.f, 0.f, 0.f, 0.f);
            int gn = col0 + nl;
            if (gn < N)
                v = *reinterpret_cast<const float4*>(Bb + (long long)gn * K + kb + k4);
            Bs[k4 + 0][nl] = v.x;
            Bs[k4 + 1][nl] = v.y;
            Bs[k4 + 2][nl] = v.z;
            Bs[k4 + 3][nl] = v.w;
        }
        __syncthreads();

        #pragma unroll
        for (int k = 0; k < BK; k++) {
            float af[8], bf[4];
            #pragma unroll
            for (int i = 0; i < 8; i++) af[i] = As[k][tm * 8 + i];
            #pragma unroll
            for (int j = 0; j < 4; j++) bf[j] = Bs[k][tn * 4 + j];
            #pragma unroll
            for (int i = 0; i < 8; i++)
                #pragma unroll
                for (int j = 0; j < 4; j++)
                    acc[i][j] = fmaf(af[i], bf[j], acc[i][j]);
        }
        __syncthreads();
    }

    #pragma unroll
    for (int i = 0; i < 8; i++) {
        int m = row0 + tm * 8 + i;
        if (m >= M) continue;
        #pragma unroll
        for (int j = 0; j < 4; j++) {
            int n = col0 + tn * 4 + j;
            if (n >= N) continue;
            float v = acc[i][j];
            if (biasb) v += biasb[n];
            long long off = (long long)m * N + n;
            if (accumulate) Cb[off] += v;
            else            Cb[off]  = v;
        }
    }
}

// ---------------------------------------------------------------------------
// Fused attention tail: score -> softmax -> weighted att sum (+optional add)
// One block per batch element b.
//   score[a] = sum_k tanh(M[b,a, col_off+k] + hh[b,a]) * d2d_w[k] + d2d_b
//   w = softmax_a(score); out[b,r] = sum_a att[b,a,r]*w[a] (+ addv[b,r])
// ---------------------------------------------------------------------------
__global__ __launch_bounds__(256)
void att_fused(const float* __restrict__ Mv, const float* __restrict__ hh,
               const float* __restrict__ att, const float* __restrict__ d2dw,
               const float* __restrict__ d2db, const float* __restrict__ addv,
               float* __restrict__ out, int col_off)
{
    const int b   = blockIdx.x;
    const int tid = threadIdx.x;

    __shared__ float wsh[A_];
    __shared__ float score[A_];
    __shared__ float red[256];

    if (tid < A_) wsh[tid] = d2dw[tid];
    __syncthreads();

    if (tid < A_) {
        const int a = tid;
        const float h = hh[b * A_ + a];
        const float4* Mrow = reinterpret_cast<const float4*>(
            Mv + ((long long)(b * A_ + a)) * KC_ + col_off);
        float s = 0.f;
        #pragma unroll 4
        for (int k4 = 0; k4 < A_ / 4; k4++) {
            float4 m = Mrow[k4];
            s += tanhf(m.x + h) * wsh[k4 * 4 + 0];
            s += tanhf(m.y + h) * wsh[k4 * 4 + 1];
            s += tanhf(m.z + h) * wsh[k4 * 4 + 2];
            s += tanhf(m.w + h) * wsh[k4 * 4 + 3];
        }
        score[a] = s + d2db[0];
    }
    __syncthreads();

    // softmax over 196 scores
    float v = (tid < A_) ? score[tid] : -INFINITY;
    red[tid] = v;
    __syncthreads();
    for (int s = 128; s > 0; s >>= 1) {
        if (tid < s) red[tid] = fmaxf(red[tid], red[tid + s]);
        __syncthreads();
    }
    const float mx = red[0];
    __syncthreads();

    float e = (tid < A_) ? expf(score[tid] - mx) : 0.f;
    red[tid] = e;
    __syncthreads();
    for (int s = 128; s > 0; s >>= 1) {
        if (tid < s) red[tid] += red[tid + s];
        __syncthreads();
    }
    const float inv = 1.f / red[0];
    __syncthreads();
    if (tid < A_) score[tid] = e * inv;  // reuse as weights
    __syncthreads();

    // weighted sum over a: out[b,r]
    for (int r = tid; r < R_; r += 256) {
        const float* ab = att + (long long)b * A_ * R_ + r;
        float acc = 0.f;
        #pragma unroll 4
        for (int a = 0; a < A_; a++)
            acc = fmaf(ab[(long long)a * R_], score[a], acc);
        if (addv) acc += addv[b * R_ + r];
        out[(long long)b * R_ + r] = acc;
    }
}

// ---------------------------------------------------------------------------
// Gate + cell update + mean over P
// ---------------------------------------------------------------------------
__global__ __launch_bounds__(256)
void gate_kernel(const float* __restrict__ sums,
                 const float* __restrict__ bi, const float* __restrict__ bh,
                 const float* __restrict__ ba,
                 const float* __restrict__ prev_c,
                 float* __restrict__ next_c, float* __restrict__ next_h)
{
    const int idx = blockIdx.x * 256 + threadIdx.x;   // over B_*R_
    const int b = idx >> 9;        // /512
    const int r = idx & (R_ - 1);
    const float pc = prev_c[idx];
    float ca = 0.f, ha = 0.f;
    #pragma unroll
    for (int p = 0; p < P_; p++) {
        const long long base = ((long long)p * B_ + b) * G4_;
        const int bb = p * G4_;
        float si = sums[base + r]           + bi[bb + r]           + bh[bb + r]           + ba[bb + r];
        float sf = sums[base + R_ + r]      + bi[bb + R_ + r]      + bh[bb + R_ + r]      + ba[bb + R_ + r];
        float so = sums[base + 2 * R_ + r]  + bi[bb + 2 * R_ + r]  + bh[bb + 2 * R_ + r]  + ba[bb + 2 * R_ + r];
        float st = sums[base + 3 * R_ + r]  + bi[bb + 3 * R_ + r]  + bh[bb + 3 * R_ + r]  + ba[bb + 3 * R_ + r];
        float ig = 1.f / (1.f + expf(-si));
        float fg = 1.f / (1.f + expf(-sf));
        float og = 1.f / (1.f + expf(-so));
        float it = tanhf(st);
        float nc = fg * pc + ig * it;
        ca += nc;
        ha += og * tanhf(nc);
    }
    next_c[idx] = ca * (1.f / 3.f);
    next_h[idx] = ha * (1.f / 3.f);
}

__global__ __launch_bounds__(256)
void add_kernel(float* __restrict__ o, const float* __restrict__ a,
                const float* __restrict__ b, int n)
{
    int i = blockIdx.x * 256 + threadIdx.x;
    if (i < n) o[i] = a[i] + b[i];
}

// ---------------------------------------------------------------------------
// In-place log-softmax over V per row (one block per b)
// ---------------------------------------------------------------------------
__global__ __launch_bounds__(256)
void logsoftmax_kernel(float* __restrict__ x)
{
    const int b   = blockIdx.x;
    const int tid = threadIdx.x;
    __shared__ float red[256];
    float* row = x + (long long)b * V_;

    float mx = -INFINITY;
    for (int i = tid; i < V_; i += 256) mx = fmaxf(mx, row[i]);
    red[tid] = mx;
    __syncthreads();
    for (int s = 128; s > 0; s >>= 1) {
        if (tid < s) red[tid] = fmaxf(red[tid], red[tid + s]);
        __syncthreads();
    }
    mx = red[0];
    __syncthreads();

    float sum = 0.f;
    for (int i = tid; i < V_; i += 256) sum += expf(row[i] - mx);
    red[tid] = sum;
    __syncthreads();
    for (int s = 128; s > 0; s >>= 1) {
        if (tid < s) red[tid] += red[tid + s];
        __syncthreads();
    }
    const float lz = logf(red[0]) + mx;
    for (int i = tid; i < V_; i += 256) row[i] = row[i] - lz;
}

// ---------------------------------------------------------------------------
// Host launch
// ---------------------------------------------------------------------------
extern "C" void kernel_launch(void* const* d_in, const int* in_sizes, int n_in,
                              void* d_out, int out_size)
{
    (void)in_sizes; (void)n_in; (void)out_size;
    const float* x      = (const float*)d_in[0];
    const float* att    = (const float*)d_in[1];
    const float* inputs = (const float*)d_in[2];
    const float* i2h_w  = (const float*)d_in[3];
    const float* i2h_b  = (const float*)d_in[4];
    const float* h2h_w  = (const float*)d_in[5];
    const float* h2h_b  = (const float*)d_in[6];
    const float* a2h_w  = (const float*)d_in[7];
    const float* a2h_b  = (const float*)d_in[8];
    const float* a2a_w  = (const float*)d_in[9];
    const float* a2a_b  = (const float*)d_in[10];
    const float* h2a_w  = (const float*)d_in[11];
    const float* h2a_b  = (const float*)d_in[12];
    const float* d2d_w  = (const float*)d_in[13];
    const float* d2d_b  = (const float*)d_in[14];
    const float* proj_w = (const float*)d_in[15];
    const float* proj_b = (const float*)d_in[16];
    float* out = (float*)d_out;

    float *pM, *phh, *patt, *psums, *pxt, *pnh;
    cudaGetSymbolAddress((void**)&pM,    gM);
    cudaGetSymbolAddress((void**)&phh,   g_hh);
    cudaGetSymbolAddress((void**)&patt,  g_att);
    cudaGetSymbolAddress((void**)&psums, g_sums);
    cudaGetSymbolAddress((void**)&pxt,   g_xt);
    cudaGetSymbolAddress((void**)&pnh,   g_nh);

    dim3 blk(256);

    // 1) All 4 calls' v = att @ a2a_w^T + a2a_b, upfront (independent of recurrence)
    {
        dim3 grid((KC_ + BN - 1) / BN, (BA_ + BM - 1) / BM, 1);
        gemm_nt<<<grid, blk>>>(att, a2a_w, pM, a2a_b,
                               BA_, KC_, R_, 0, 0, 0, 0, 0);
    }

    const size_t wst = (size_t)G4_ * R_;  // per-p weight stride

    for (int i = 0; i < L_; i++) {
        const float* prev_c = inputs + (size_t)(2 * i) * B_ * R_;
        const float* prev_h = inputs + (size_t)(2 * i + 1) * B_ * R_;
        const float* xt;
        if (i == 0) {
            xt = x;
        } else {
            add_kernel<<<(B_ * R_ + 255) / 256, blk>>>(pxt, x, out + (size_t)1 * B_ * R_, B_ * R_);
            xt = pxt;
        }

        // --- soft_att call 0 (uses prev_h) ---
        const int c0 = 2 * i;
        {
            dim3 g((A_ + BN - 1) / BN, (B_ + BM - 1) / BM, 1);
            gemm_nt<<<g, blk>>>(prev_h, h2a_w + (size_t)c0 * A_ * R_, phh,
                                h2a_b + (size_t)c0 * A_,
                                B_, A_, R_, 0, 0, 0, 0, 0);
        }
        att_fused<<<B_, blk>>>(pM, phh, att, d2d_w + (size_t)c0 * A_,
                               d2d_b + c0, nullptr, patt, c0 * A_);

        // --- LSTM gate pre-activations: 3 accumulating batched GEMMs over p ---
        {
            dim3 g((G4_ + BN - 1) / BN, (B_ + BM - 1) / BM, P_);
            gemm_nt<<<g, blk>>>(xt,     i2h_w + (size_t)i * P_ * wst, psums, nullptr,
                                B_, G4_, R_, 0, (long long)wst, (long long)B_ * G4_, 0, 0);
            gemm_nt<<<g, blk>>>(prev_h, h2h_w + (size_t)i * P_ * wst, psums, nullptr,
                                B_, G4_, R_, 0, (long long)wst, (long long)B_ * G4_, 0, 1);
            gemm_nt<<<g, blk>>>(patt,   a2h_w + (size_t)i * P_ * wst, psums, nullptr,
                                B_, G4_, R_, 0, (long long)wst, (long long)B_ * G4_, 0, 1);
        }

        // --- gates, cell update, mean over p; next_c -> d_out slot 2i ---
        gate_kernel<<<(B_ * R_) / 256, blk>>>(psums,
                                              i2h_b + (size_t)i * P_ * G4_,
                                              h2h_b + (size_t)i * P_ * G4_,
                                              a2h_b + (size_t)i * P_ * G4_,
                                              prev_c,
                                              out + (size_t)(2 * i) * B_ * R_, pnh);

        // --- soft_att call 1 (uses next_h) ; top_h -> d_out slot 2i+1 ---
        const int c1 = 2 * i + 1;
        {
            dim3 g((A_ + BN - 1) / BN, (B_ + BM - 1) / BM, 1);
            gemm_nt<<<g, blk>>>(pnh, h2a_w + (size_t)c1 * A_ * R_, phh,
                                h2a_b + (size_t)c1 * A_,
                                B_, A_, R_, 0, 0, 0, 0, 0);
        }
        att_fused<<<B_, blk>>>(pM, phh, att, d2d_w + (size_t)c1 * A_,
                               d2d_b + c1, pnh,
                               out + (size_t)(2 * i + 1) * B_ * R_, c1 * A_);
    }

    // 2) projection + log-softmax (top_h of layer 1 lives in d_out slot 3)
    {
        dim3 g((V_ + BN - 1) / BN, (B_ + BM - 1) / BM, 1);
        gemm_nt<<<g, blk>>>(out + (size_t)3 * B_ * R_, proj_w,
                            out + (size_t)4 * B_ * R_, proj_b,
                            B_, V_, R_, 0, 0, 0, 0, 0);
    }
    logsoftmax_kernel<<<B_, blk>>>(out + (size_t)4 * B_ * R_);
}

// round 3
// speedup vs baseline: 2.2433x; 2.2433x over previous
#include <cuda_runtime.h>
#include <math.h>
#include <stdint.h>

// Problem constants
#define L_   2
#define P_   3
#define R_   512
#define A_   196
#define V_   9487
#define B_   256
#define BA_  (B_*A_)        // 50176
#define KC_  (2*L_*A_)      // 784
#define G4_  (4*R_)         // 2048

// ---------------------------------------------------------------------------
// Static device scratch (allocation-free)
// ---------------------------------------------------------------------------
__device__ float gM   [(size_t)BA_ * KC_];  // 50176 x 784 pre-tanh attention logits
__device__ float g_hh2[2 * B_ * A_];        // hh for call0 of both layers
__device__ float g_hh [B_ * A_];
__device__ float g_att0[2 * B_ * R_];       // att_res0 for both layers
__device__ float g_sums[P_ * B_ * G4_];
__device__ float g_cat [B_ * 3 * R_];       // packed [xt; prev_h; att_res]
__device__ float g_nh  [B_ * R_];

// ---------------------------------------------------------------------------
// Fast math on the FMA/ALU pipes (no MUFU)
// ---------------------------------------------------------------------------
__device__ __forceinline__ float exp2_poly(float g) {
    // 2^g, g in [-0.5, 0.5]
    float p = 1.5402387e-4f;
    p = fmaf(p, g, 1.3333558146e-3f);
    p = fmaf(p, g, 9.6181291076e-3f);
    p = fmaf(p, g, 5.5504108664e-2f);
    p = fmaf(p, g, 2.4022650696e-1f);
    p = fmaf(p, g, 6.9314718056e-1f);
    p = fmaf(p, g, 1.0f);
    return p;
}
__device__ __forceinline__ float fast_tanh(float x) {
    float ax = fabsf(x);
    float t  = fminf(ax * 2.8853900817779268f, 30.0f);  // 2*log2(e)*|x|
    int   ni = __float2int_rn(t);
    float f  = t - (float)ni;                           // [-0.5, 0.5]
    float p  = exp2_poly(-f);
    float sc = __int_as_float((127 - ni) << 23);        // 2^-ni
    float u  = p * sc;                                  // e^{-2|x|}
    float d  = 1.0f + u;                                // [1, 2]
    float r  = fmaf(d, -0.5f, 1.457107f);               // ~1/d + Newton x3
    r = r * fmaf(-d, r, 2.0f);
    r = r * fmaf(-d, r, 2.0f);
    r = r * fmaf(-d, r, 2.0f);
    float th = (1.0f - u) * r;
    return copysignf(th, x);
}
__device__ __forceinline__ float fast_expf(float x) {
    float t  = fmaxf(x * 1.4426950408889634f, -126.0f);
    int   ni = __float2int_rn(t);
    float f  = t - (float)ni;
    float p  = exp2_poly(f);
    float sc = __int_as_float((ni + 127) << 23);
    return p * sc;
}
__device__ __forceinline__ float fast_sigmoid(float x) {
    return fmaf(fast_tanh(0.5f * x), 0.5f, 0.5f);
}

// ---------------------------------------------------------------------------
// fp32 -> tf32 round-to-nearest
// ---------------------------------------------------------------------------
__device__ __forceinline__ uint32_t f2tf32(float x) {
    uint32_t r;
    asm("cvt.rna.tf32.f32 %0, %1;" : "=r"(r) : "f"(x));
    return r;
}

#define MMA_TF32(c, a, b) \
    asm volatile("mma.sync.aligned.m16n8k8.row.col.f32.tf32.tf32.f32 " \
        "{%0,%1,%2,%3}, {%4,%5,%6,%7}, {%8,%9}, {%0,%1,%2,%3};" \
        : "+f"((c)[0]), "+f"((c)[1]), "+f"((c)[2]), "+f"((c)[3]) \
        : "r"((a)[0]), "r"((a)[1]), "r"((a)[2]), "r"((a)[3]), \
          "r"((b)[0]), "r"((b)[1]))

// ---------------------------------------------------------------------------
// mma.sync tf32 NT GEMM:  C[m,n] = sum_k A[m,k]*B[n,k] (+bias[n])
// Block 128x128, BK=32, 8 warps (4x2), warp tile 32x64.
// A: [M, lda], M multiple of 128. B: K-segmented (512 each), row stride 512.
// Batched over blockIdx.z (strides sA/sB/sC/sBias).
// Single smem buffer, register-staged global loads, SW128 XOR swizzle.
// ---------------------------------------------------------------------------
__global__ __launch_bounds__(256, 2)
void gemm_mma(const float* __restrict__ A,
              const float* __restrict__ B0, const float* __restrict__ B1,
              const float* __restrict__ B2,
              float* __restrict__ C, const float* __restrict__ bias,
              int N, int Ktot, int lda, int ldc,
              long long sA, long long sB, long long sC, long long sBias)
{
    __shared__ __align__(16) uint32_t smA[128 * 32];
    __shared__ __align__(16) uint32_t smB[128 * 32];

    const int tid   = threadIdx.x;
    const int warp  = tid >> 5;
    const int lane  = tid & 31;
    const int gid   = lane >> 2;       // 0..7
    const int tig   = lane & 3;        // 0..3
    const int warpM = warp & 3;        // 0..3
    const int warpN = warp >> 2;       // 0..1
    const int mbase = warpM * 32;
    const int nbase = warpN * 64;

    const int row0 = blockIdx.y * 128;
    const int col0 = blockIdx.x * 128;
    const int z    = blockIdx.z;

    const float* Az = A + (long long)z * sA;
    float*       Cz = C + (long long)z * sC;

    // per-thread staging indices
    const int sr  = tid >> 3;          // row within tile (0..31 step: tid/8)
    const int sc4 = tid & 7;           // 16B chunk within 128B row

    float4 gA[4], gB[4];

    // clamp B row helper data
    auto segptr = [&](int kb) -> const float* {
        const int seg = kb >> 9;
        const float* Bp = (seg == 0) ? B0 : (seg == 1) ? B1 : B2;
        return Bp + (long long)z * sB;
    };

    // prologue loads (chunk 0)
    {
        const float* Bp = segptr(0);
        #pragma unroll
        for (int j = 0; j < 4; j++) {
            int r = sr + j * 32;
            gA[j] = *reinterpret_cast<const float4*>(
                Az + (long long)(row0 + r) * lda + sc4 * 4);
            int n = col0 + r; if (n >= N) n = N - 1;
            gB[j] = *reinterpret_cast<const float4*>(
                Bp + (long long)n * 512 + sc4 * 4);
        }
    }

    float acc[2][8][4];
    #pragma unroll
    for (int mt = 0; mt < 2; mt++)
        #pragma unroll
        for (int nt = 0; nt < 8; nt++)
            #pragma unroll
            for (int q = 0; q < 4; q++) acc[mt][nt][q] = 0.f;

    const int ncc = Ktot >> 5;
    for (int cc = 0; cc < ncc; cc++) {
        __syncthreads();   // previous compute done; smem reusable
        // STS with swizzle + RNA tf32 conversion
        #pragma unroll
        for (int j = 0; j < 4; j++) {
            int r = sr + j * 32;
            uint32_t off = r * 32 + ((sc4 ^ (r & 7)) << 2);
            uint4 va, vb;
            va.x = f2tf32(gA[j].x); va.y = f2tf32(gA[j].y);
            va.z = f2tf32(gA[j].z); va.w = f2tf32(gA[j].w);
            vb.x = f2tf32(gB[j].x); vb.y = f2tf32(gB[j].y);
            vb.z = f2tf32(gB[j].z); vb.w = f2tf32(gB[j].w);
            *reinterpret_cast<uint4*>(&smA[off]) = va;
            *reinterpret_cast<uint4*>(&smB[off]) = vb;
        }
        __syncthreads();

        // prefetch next chunk while computing this one
        if (cc + 1 < ncc) {
            const int kb = (cc + 1) << 5;
            const float* Bp = segptr(kb);
            const int kbl = kb & 511;
            #pragma unroll
            for (int j = 0; j < 4; j++) {
                int r = sr + j * 32;
                gA[j] = *reinterpret_cast<const float4*>(
                    Az + (long long)(row0 + r) * lda + kb + sc4 * 4);
                int n = col0 + r; if (n >= N) n = N - 1;
                gB[j] = *reinterpret_cast<const float4*>(
                    Bp + (long long)n * 512 + kbl + sc4 * 4);
            }
        }

        // compute: 4 k-steps of 8
        #pragma unroll
        for (int ks = 0; ks < 4; ks++) {
            const int k4 = ks * 2;
            uint32_t aF[2][4];
            #pragma unroll
            for (int mt = 0; mt < 2; mt++) {
                const int ml = mbase + mt * 16 + gid;
                const int mh = ml + 8;
                const uint32_t x0 = ((k4 ^ gid) << 2) + tig;
                const uint32_t x1 = (((k4 + 1) ^ gid) << 2) + tig;
                aF[mt][0] = smA[ml * 32 + x0];
                aF[mt][1] = smA[mh * 32 + x0];
                aF[mt][2] = smA[ml * 32 + x1];
                aF[mt][3] = smA[mh * 32 + x1];
            }
            #pragma unroll
            for (int nt = 0; nt < 8; nt++) {
                const int n = nbase + nt * 8 + gid;
                const uint32_t x0 = ((k4 ^ gid) << 2) + tig;
                const uint32_t x1 = (((k4 + 1) ^ gid) << 2) + tig;
                uint32_t bF[2];
                bF[0] = smB[n * 32 + x0];
                bF[1] = smB[n * 32 + x1];
                MMA_TF32(acc[0][nt], aF[0], bF);
                MMA_TF32(acc[1][nt], aF[1], bF);
            }
        }
    }

    // Epilogue
    const float* bz = bias ? (bias + (long long)z * sBias) : nullptr;
    const bool even = ((ldc & 1) == 0);
    #pragma unroll
    for (int mt = 0; mt < 2; mt++) {
        const int rlo = row0 + mbase + mt * 16 + gid;
        const int rhi = rlo + 8;
        #pragma unroll
        for (int nt = 0; nt < 8; nt++) {
            const int n0 = col0 + nbase + nt * 8 + 2 * tig;
            if (n0 >= N) continue;
            float b0v = bz ? bz[n0] : 0.f;
            float b1v = (bz && n0 + 1 < N) ? bz[n0 + 1] : 0.f;
            float c0 = acc[mt][nt][0] + b0v;
            float c1 = acc[mt][nt][1] + b1v;
            float c2 = acc[mt][nt][2] + b0v;
            float c3 = acc[mt][nt][3] + b1v;
            if (even && (n0 + 1 < N)) {
                *reinterpret_cast<float2*>(Cz + (long long)rlo * ldc + n0) = make_float2(c0, c1);
                *reinterpret_cast<float2*>(Cz + (long long)rhi * ldc + n0) = make_float2(c2, c3);
            } else {
                Cz[(long long)rlo * ldc + n0] = c0;
                Cz[(long long)rhi * ldc + n0] = c2;
                if (n0 + 1 < N) {
                    Cz[(long long)rlo * ldc + n0 + 1] = c1;
                    Cz[(long long)rhi * ldc + n0 + 1] = c3;
                }
            }
        }
    }
}

// ---------------------------------------------------------------------------
// Fused attention (both layers' call0 in one pass over att)
// ---------------------------------------------------------------------------
__global__ __launch_bounds__(256)
void att_res0_kernel(const float* __restrict__ Mv, const float* __restrict__ hh2,
                     const float* __restrict__ att, const float* __restrict__ d2dw,
                     const float* __restrict__ d2db, float* __restrict__ outp)
{
    const int b = blockIdx.x, tid = threadIdx.x;
    __shared__ float ws[2][A_];
    __shared__ float red[256];

    #pragma unroll
    for (int lyr = 0; lyr < 2; lyr++) {
        const int call = lyr * 2;
        float sc = -INFINITY;
        if (tid < A_) {
            const int a = tid;
            const float h = hh2[lyr * B_ * A_ + b * A_ + a];
            const float* w = d2dw + call * A_;
            const float4* Mrow = reinterpret_cast<const float4*>(
                Mv + ((long long)(b * A_ + a)) * KC_ + call * A_);
            float s = 0.f;
            #pragma unroll 4
            for (int k4 = 0; k4 < A_ / 4; k4++) {
                float4 m = Mrow[k4];
                s = fmaf(fast_tanh(m.x + h), w[4 * k4 + 0], s);
                s = fmaf(fast_tanh(m.y + h), w[4 * k4 + 1], s);
                s = fmaf(fast_tanh(m.z + h), w[4 * k4 + 2], s);
                s = fmaf(fast_tanh(m.w + h), w[4 * k4 + 3], s);
            }
            sc = s + d2db[call];
        }
        red[tid] = sc; __syncthreads();
        for (int s = 128; s > 0; s >>= 1) {
            if (tid < s) red[tid] = fmaxf(red[tid], red[tid + s]);
            __syncthreads();
        }
        const float mx = red[0]; __syncthreads();
        float e = (tid < A_) ? fast_expf(sc - mx) : 0.f;
        red[tid] = e; __syncthreads();
        for (int s = 128; s > 0; s >>= 1) {
            if (tid < s) red[tid] += red[tid + s];
            __syncthreads();
        }
        const float inv = 1.f / red[0]; __syncthreads();
        if (tid < A_) ws[lyr][tid] = e * inv;
        __syncthreads();
    }

    for (int r = tid; r < R_; r += 256) {
        const float* ab = att + (long long)b * A_ * R_ + r;
        float a0 = 0.f, a1 = 0.f;
        #pragma unroll 4
        for (int a = 0; a < A_; a++) {
            float v = ab[(long long)a * R_];
            a0 = fmaf(v, ws[0][a], a0);
            a1 = fmaf(v, ws[1][a], a1);
        }
        outp[b * R_ + r]           = a0;
        outp[B_ * R_ + b * R_ + r] = a1;
    }
}

// Single-call fused attention (call1, depends on next_h)
__global__ __launch_bounds__(256)
void att_fused(const float* __restrict__ Mv, const float* __restrict__ hh,
               const float* __restrict__ att, const float* __restrict__ d2dw,
               const float* __restrict__ d2db, const float* __restrict__ addv,
               float* __restrict__ out, int col_off)
{
    const int b = blockIdx.x, tid = threadIdx.x;
    __shared__ float ws[A_];
    __shared__ float red[256];

    float sc = -INFINITY;
    if (tid < A_) {
        const int a = tid;
        const float h = hh[b * A_ + a];
        const float4* Mrow = reinterpret_cast<const float4*>(
            Mv + ((long long)(b * A_ + a)) * KC_ + col_off);
        float s = 0.f;
        #pragma unroll 4
        for (int k4 = 0; k4 < A_ / 4; k4++) {
            float4 m = Mrow[k4];
            s = fmaf(fast_tanh(m.x + h), d2dw[4 * k4 + 0], s);
            s = fmaf(fast_tanh(m.y + h), d2dw[4 * k4 + 1], s);
            s = fmaf(fast_tanh(m.z + h), d2dw[4 * k4 + 2], s);
            s = fmaf(fast_tanh(m.w + h), d2dw[4 * k4 + 3], s);
        }
        sc = s + d2db[0];
    }
    red[tid] = sc; __syncthreads();
    for (int s = 128; s > 0; s >>= 1) {
        if (tid < s) red[tid] = fmaxf(red[tid], red[tid + s]);
        __syncthreads();
    }
    const float mx = red[0]; __syncthreads();
    float e = (tid < A_) ? fast_expf(sc - mx) : 0.f;
    red[tid] = e; __syncthreads();
    for (int s = 128; s > 0; s >>= 1) {
        if (tid < s) red[tid] += red[tid + s];
        __syncthreads();
    }
    const float inv = 1.f / red[0]; __syncthreads();
    if (tid < A_) ws[tid] = e * inv;
    __syncthreads();

    for (int r = tid; r < R_; r += 256) {
        const float* ab = att + (long long)b * A_ * R_ + r;
        float acc = 0.f;
        #pragma unroll 4
        for (int a = 0; a < A_; a++)
            acc = fmaf(ab[(long long)a * R_], ws[a], acc);
        if (addv) acc += addv[b * R_ + r];
        out[(long long)b * R_ + r] = acc;
    }
}

// ---------------------------------------------------------------------------
// Pack [xt; prev_h; att_res] into g_cat
// ---------------------------------------------------------------------------
__global__ __launch_bounds__(256)
void pack_cat(const float* __restrict__ x, const float* __restrict__ add,
              const float* __restrict__ ph, const float* __restrict__ ar,
              float* __restrict__ cat)
{
    const int idx = blockIdx.x * 256 + threadIdx.x;
    const int b = idx >> 9, r = idx & (R_ - 1);
    float xv = x[idx];
    if (add) xv += add[idx];
    cat[b * 3 * R_ + r]          = xv;
    cat[b * 3 * R_ + R_ + r]     = ph[idx];
    cat[b * 3 * R_ + 2 * R_ + r] = ar[idx];
}

// ---------------------------------------------------------------------------
// Gates + cell update + mean over P
// ---------------------------------------------------------------------------
__global__ __launch_bounds__(256)
void gate_kernel(const float* __restrict__ sums,
                 const float* __restrict__ bi, const float* __restrict__ bh,
                 const float* __restrict__ ba,
                 const float* __restrict__ prev_c,
                 float* __restrict__ next_c, float* __restrict__ next_h)
{
    const int idx = blockIdx.x * 256 + threadIdx.x;
    const int b = idx >> 9, r = idx & (R_ - 1);
    const float pc = prev_c[idx];
    float ca = 0.f, ha = 0.f;
    #pragma unroll
    for (int p = 0; p < P_; p++) {
        const long long base = ((long long)p * B_ + b) * G4_;
        const int bb = p * G4_;
        float si = sums[base + r]        + bi[bb + r]        + bh[bb + r]        + ba[bb + r];
        float sf = sums[base + R_ + r]   + bi[bb + R_ + r]   + bh[bb + R_ + r]   + ba[bb + R_ + r];
        float so = sums[base + 2*R_ + r] + bi[bb + 2*R_ + r] + bh[bb + 2*R_ + r] + ba[bb + 2*R_ + r];
        float st = sums[base + 3*R_ + r] + bi[bb + 3*R_ + r] + bh[bb + 3*R_ + r] + ba[bb + 3*R_ + r];
        float ig = fast_sigmoid(si);
        float fg = fast_sigmoid(sf);
        float og = fast_sigmoid(so);
        float it = fast_tanh(st);
        float nc = fg * pc + ig * it;
        ca += nc;
        ha += og * fast_tanh(nc);
    }
    next_c[idx] = ca * (1.f / 3.f);
    next_h[idx] = ha * (1.f / 3.f);
}

// ---------------------------------------------------------------------------
// In-place log-softmax over V per row
// ---------------------------------------------------------------------------
__global__ __launch_bounds__(256)
void logsoftmax_kernel(float* __restrict__ x)
{
    const int b = blockIdx.x, tid = threadIdx.x;
    __shared__ float red[256];
    float* row = x + (long long)b * V_;

    float mx = -INFINITY;
    for (int i = tid; i < V_; i += 256) mx = fmaxf(mx, row[i]);
    red[tid] = mx; __syncthreads();
    for (int s = 128; s > 0; s >>= 1) {
        if (tid < s) red[tid] = fmaxf(red[tid], red[tid + s]);
        __syncthreads();
    }
    mx = red[0]; __syncthreads();

    float sum = 0.f;
    for (int i = tid; i < V_; i += 256) sum += fast_expf(row[i] - mx);
    red[tid] = sum; __syncthreads();
    for (int s = 128; s > 0; s >>= 1) {
        if (tid < s) red[tid] += red[tid + s];
        __syncthreads();
    }
    const float lz = logf(red[0]) + mx;
    for (int i = tid; i < V_; i += 256) row[i] = row[i] - lz;
}

// ---------------------------------------------------------------------------
// Host launch
// ---------------------------------------------------------------------------
extern "C" void kernel_launch(void* const* d_in, const int* in_sizes, int n_in,
                              void* d_out, int out_size)
{
    (void)in_sizes; (void)n_in; (void)out_size;
    const float* x      = (const float*)d_in[0];
    const float* att    = (const float*)d_in[1];
    const float* inputs = (const float*)d_in[2];
    const float* i2h_w  = (const float*)d_in[3];
    const float* i2h_b  = (const float*)d_in[4];
    const float* h2h_w  = (const float*)d_in[5];
    const float* h2h_b  = (const float*)d_in[6];
    const float* a2h_w  = (const float*)d_in[7];
    const float* a2h_b  = (const float*)d_in[8];
    const float* a2a_w  = (const float*)d_in[9];
    const float* a2a_b  = (const float*)d_in[10];
    const float* h2a_w  = (const float*)d_in[11];
    const float* h2a_b  = (const float*)d_in[12];
    const float* d2d_w  = (const float*)d_in[13];
    const float* d2d_b  = (const float*)d_in[14];
    const float* proj_w = (const float*)d_in[15];
    const float* proj_b = (const float*)d_in[16];
    float* out = (float*)d_out;

    float *pM, *phh2, *phh, *patt0, *psums, *pcat, *pnh;
    cudaGetSymbolAddress((void**)&pM,    gM);
    cudaGetSymbolAddress((void**)&phh2,  g_hh2);
    cudaGetSymbolAddress((void**)&phh,   g_hh);
    cudaGetSymbolAddress((void**)&patt0, g_att0);
    cudaGetSymbolAddress((void**)&psums, g_sums);
    cudaGetSymbolAddress((void**)&pcat,  g_cat);
    cudaGetSymbolAddress((void**)&pnh,   g_nh);

    dim3 blk(256);
    const size_t wst = (size_t)G4_ * R_;   // per-p weight stride

    // 1) Big logits GEMM: gM = att @ a2a_w^T + a2a_b   (50176 x 784 x 512)
    gemm_mma<<<dim3(7, BA_ / 128, 1), blk>>>(
        att, a2a_w, nullptr, nullptr, pM, a2a_b,
        KC_, R_, R_, KC_, 0, 0, 0, 0);

    // 2) hh for call0 of both layers (batched z=layer)
    gemm_mma<<<dim3(2, 2, 2), blk>>>(
        inputs + (size_t)B_ * R_, h2a_w, nullptr, nullptr, phh2, h2a_b,
        A_, R_, R_, A_,
        (long long)2 * B_ * R_, (long long)2 * A_ * R_,
        (long long)B_ * A_, (long long)2 * A_);

    // 3) att_res0 for both layers in one pass over att
    att_res0_kernel<<<B_, blk>>>(pM, phh2, att, d2d_w, d2d_b, patt0);

    for (int i = 0; i < L_; i++) {
        const float* prev_c = inputs + (size_t)(2 * i) * B_ * R_;
        const float* prev_h = inputs + (size_t)(2 * i + 1) * B_ * R_;

        pack_cat<<<(B_ * R_) / 256, blk>>>(
            x, (i == 0) ? nullptr : (out + (size_t)1 * B_ * R_),
            prev_h, patt0 + (size_t)i * B_ * R_, pcat);

        // fused gate GEMM: K=1536 segmented across the three weight tensors
        gemm_mma<<<dim3(16, 2, P_), blk>>>(
            pcat,
            i2h_w + (size_t)i * P_ * wst,
            h2h_w + (size_t)i * P_ * wst,
            a2h_w + (size_t)i * P_ * wst,
            psums, nullptr,
            G4_, 3 * R_, 3 * R_, G4_,
            0, (long long)wst, (long long)B_ * G4_, 0);

        gate_kernel<<<(B_ * R_) / 256, blk>>>(
            psums,
            i2h_b + (size_t)i * P_ * G4_,
            h2h_b + (size_t)i * P_ * G4_,
            a2h_b + (size_t)i * P_ * G4_,
            prev_c,
            out + (size_t)(2 * i) * B_ * R_, pnh);

        const int c1 = 2 * i + 1;
        gemm_mma<<<dim3(2, 2, 1), blk>>>(
            pnh, h2a_w + (size_t)c1 * A_ * R_, nullptr, nullptr, phh,
            h2a_b + (size_t)c1 * A_,
            A_, R_, R_, A_, 0, 0, 0, 0);

        att_fused<<<B_, blk>>>(pM, phh, att, d2d_w + (size_t)c1 * A_,
                               d2d_b + c1, pnh,
                               out + (size_t)(2 * i + 1) * B_ * R_, c1 * A_);
    }

    // projection + log-softmax
    gemm_mma<<<dim3(75, 2, 1), blk>>>(
        out + (size_t)3 * B_ * R_, proj_w, nullptr, nullptr,
        out + (size_t)4 * B_ * R_, proj_b,
        V_, R_, R_, V_, 0, 0, 0, 0);
    logsoftmax_kernel<<<B_, blk>>>(out + (size_t)4 * B_ * R_);
}

// round 4
// speedup vs baseline: 3.4541x; 1.5397x over previous
#include <cuda_runtime.h>
#include <math.h>
#include <stdint.h>

// Problem constants
#define L_   2
#define P_   3
#define R_   512
#define A_   196
#define V_   9487
#define B_   256
#define BA_  (B_*A_)        // 50176
#define KC_  (2*L_*A_)      // 784
#define G4_  (4*R_)         // 2048

// ---------------------------------------------------------------------------
// Static device scratch (allocation-free)
// ---------------------------------------------------------------------------
__device__ float gM    [(size_t)BA_ * KC_]; // 50176 x 784 pre-tanh attention logits
__device__ float g_hh2 [2 * B_ * A_];
__device__ float g_hh  [B_ * A_];
__device__ float g_score[2 * BA_];
__device__ float g_ws  [2 * BA_];
__device__ float g_att0[2 * B_ * R_];
__device__ float g_sums[P_ * B_ * G4_];
__device__ float g_xt  [B_ * R_];
__device__ float g_nh  [B_ * R_];

// ---------------------------------------------------------------------------
// Fast math on the FMA/ALU pipes (no MUFU)
// ---------------------------------------------------------------------------
__device__ __forceinline__ float exp2_poly(float g) {
    float p = 1.5402387e-4f;
    p = fmaf(p, g, 1.3333558146e-3f);
    p = fmaf(p, g, 9.6181291076e-3f);
    p = fmaf(p, g, 5.5504108664e-2f);
    p = fmaf(p, g, 2.4022650696e-1f);
    p = fmaf(p, g, 6.9314718056e-1f);
    p = fmaf(p, g, 1.0f);
    return p;
}
__device__ __forceinline__ float fast_tanh(float x) {
    float ax = fabsf(x);
    float t  = fminf(ax * 2.8853900817779268f, 30.0f);
    int   ni = __float2int_rn(t);
    float f  = t - (float)ni;
    float p  = exp2_poly(-f);
    float sc = __int_as_float((127 - ni) << 23);
    float u  = p * sc;                  // e^{-2|x|}
    float d  = 1.0f + u;                // [1,2]
    float r  = fmaf(d, -0.5f, 1.457107f);
    r = r * fmaf(-d, r, 2.0f);
    r = r * fmaf(-d, r, 2.0f);
    float th = (1.0f - u) * r;
    return copysignf(th, x);
}
__device__ __forceinline__ float fast_expf(float x) {
    float t  = fmaxf(x * 1.4426950408889634f, -126.0f);
    int   ni = __float2int_rn(t);
    float f  = t - (float)ni;
    float p  = exp2_poly(f);
    float sc = __int_as_float((ni + 127) << 23);
    return p * sc;
}
__device__ __forceinline__ float fast_sigmoid(float x) {
    return fmaf(fast_tanh(0.5f * x), 0.5f, 0.5f);
}

// ---------------------------------------------------------------------------
// mma / cp.async helpers
// ---------------------------------------------------------------------------
#define MMA_TF32(c, a, b) \
    asm volatile("mma.sync.aligned.m16n8k8.row.col.f32.tf32.tf32.f32 " \
        "{%0,%1,%2,%3}, {%4,%5,%6,%7}, {%8,%9}, {%0,%1,%2,%3};" \
        : "+f"((c)[0]), "+f"((c)[1]), "+f"((c)[2]), "+f"((c)[3]) \
        : "r"((a)[0]), "r"((a)[1]), "r"((a)[2]), "r"((a)[3]), \
          "r"((b)[0]), "r"((b)[1]))

__device__ __forceinline__ uint32_t smem_u32(const void* p) {
    uint32_t a;
    asm("{ .reg .u64 t; cvta.to.shared.u64 t, %1; cvt.u32.u64 %0, t; }" : "=r"(a) : "l"(p));
    return a;
}
__device__ __forceinline__ void cp16(uint32_t dst, const void* src) {
    asm volatile("cp.async.cg.shared.global [%0], [%1], 16;" :: "r"(dst), "l"(src));
}
#define CP_COMMIT() asm volatile("cp.async.commit_group;" ::: "memory")
#define CP_WAIT1()  asm volatile("cp.async.wait_group 1;" ::: "memory")

// ---------------------------------------------------------------------------
// Pipelined mma.sync tf32 NT GEMM:  C[m,n] = sum_k A[m,k]*B[n,k] (+bias[n])
// Block 128 x BN, BK=32, 3-stage cp.async pipeline, 8 warps (4x2).
// A and B both K-segmented into up to 3 sources of 512 K each; all operand
// rows have stride 512 floats. M must be a multiple of 128.
// Batched over blockIdx.z (strides sA/sB/sC/sBias).
// ---------------------------------------------------------------------------
template<int BN>
__global__ __launch_bounds__(256, 2)
void gemm_mma(const float* __restrict__ A0, const float* __restrict__ A1,
              const float* __restrict__ A2,
              const float* __restrict__ B0, const float* __restrict__ B1,
              const float* __restrict__ B2,
              float* __restrict__ C, const float* __restrict__ bias,
              int N, int Ktot, int ldc,
              long long sA, long long sB, long long sC, long long sBias)
{
    constexpr int NT    = BN / 16;         // n-tiles per warp
    constexpr int AW    = 128 * 32;        // floats per A stage
    constexpr int BW    = BN * 32;
    constexpr int STAGE = AW + BW;

    extern __shared__ float sm[];

    const int tid   = threadIdx.x;
    const int warp  = tid >> 5;
    const int lane  = tid & 31;
    const int gid   = lane >> 2;
    const int tig   = lane & 3;
    const int mbase = (warp & 3) * 32;
    const int nbase = (warp >> 2) * (BN / 2);

    const int row0 = blockIdx.y * 128;
    const int col0 = blockIdx.x * BN;
    const int z    = blockIdx.z;

    const int sr  = tid >> 3;              // 0..31
    const int sc4 = tid & 7;               // 16B chunk
    const uint32_t smbase = smem_u32(sm);
    const uint32_t swoff  = (uint32_t)((sc4 ^ (sr & 7)) << 2); // same for rows sr+32j

    const int ncc = Ktot >> 5;

    auto issue = [&](int cc) {
        if (cc < ncc) {
            const int kb  = cc << 5;
            const int seg = kb >> 9;
            const int kbl = kb & 511;
            const float* Ap = ((seg == 0) ? A0 : (seg == 1) ? A1 : A2)
                              + (long long)z * sA + kbl + sc4 * 4;
            const float* Bp = ((seg == 0) ? B0 : (seg == 1) ? B1 : B2)
                              + (long long)z * sB + kbl + sc4 * 4;
            const uint32_t stA = smbase + (uint32_t)(cc % 3) * (STAGE * 4);
            const uint32_t stB = stA + AW * 4;
            #pragma unroll
            for (int j = 0; j < 4; j++) {
                int r = sr + j * 32;
                cp16(stA + (r * 32) * 4 + swoff * 4,
                     Ap + (long long)(row0 + r) * 512);
            }
            #pragma unroll
            for (int j = 0; j < BN / 32; j++) {
                int r = sr + j * 32;
                int n = col0 + r; if (n >= N) n = N - 1;
                cp16(stB + (r * 32) * 4 + swoff * 4,
                     Bp + (long long)n * 512);
            }
        }
        CP_COMMIT();
    };

    float acc[2][NT][4];
    #pragma unroll
    for (int mt = 0; mt < 2; mt++)
        #pragma unroll
        for (int nt = 0; nt < NT; nt++)
            #pragma unroll
            for (int q = 0; q < 4; q++) acc[mt][nt][q] = 0.f;

    issue(0);
    issue(1);

    for (int cc = 0; cc < ncc; cc++) {
        CP_WAIT1();
        __syncthreads();                    // stage cc%3 visible; prior compute done
        issue(cc + 2);                      // overwrites stage (cc-1)%3 — safe post-sync

        const uint32_t* uA = reinterpret_cast<const uint32_t*>(sm + (cc % 3) * STAGE);
        const uint32_t* uB = uA + AW;

        #pragma unroll
        for (int ks = 0; ks < 4; ks++) {
            const int k4 = ks * 2;
            const uint32_t x0 = (uint32_t)(((k4 ^ gid) << 2) + tig);
            const uint32_t x1 = (uint32_t)((((k4 + 1) ^ gid) << 2) + tig);
            uint32_t aF[2][4];
            #pragma unroll
            for (int mt = 0; mt < 2; mt++) {
                const int ml = mbase + mt * 16 + gid;
                const int mh = ml + 8;
                aF[mt][0] = uA[ml * 32 + x0];
                aF[mt][1] = uA[mh * 32 + x0];
                aF[mt][2] = uA[ml * 32 + x1];
                aF[mt][3] = uA[mh * 32 + x1];
            }
            #pragma unroll
            for (int nt = 0; nt < NT; nt++) {
                const int n = nbase + nt * 8 + gid;
                uint32_t bF[2];
                bF[0] = uB[n * 32 + x0];
                bF[1] = uB[n * 32 + x1];
                MMA_TF32(acc[0][nt], aF[0], bF);
                MMA_TF32(acc[1][nt], aF[1], bF);
            }
        }
    }

    // Epilogue
    float* Cz = C + (long long)z * sC;
    const float* bz = bias ? (bias + (long long)z * sBias) : nullptr;
    const bool even = ((ldc & 1) == 0);
    #pragma unroll
    for (int mt = 0; mt < 2; mt++) {
        const int rlo = row0 + mbase + mt * 16 + gid;
        const int rhi = rlo + 8;
        #pragma unroll
        for (int nt = 0; nt < NT; nt++) {
            const int n0 = col0 + nbase + nt * 8 + 2 * tig;
            if (n0 >= N) continue;
            float b0v = bz ? bz[n0] : 0.f;
            float b1v = (bz && n0 + 1 < N) ? bz[n0 + 1] : 0.f;
            float c0 = acc[mt][nt][0] + b0v;
            float c1 = acc[mt][nt][1] + b1v;
            float c2 = acc[mt][nt][2] + b0v;
            float c3 = acc[mt][nt][3] + b1v;
            if (even && (n0 + 1 < N)) {
                *reinterpret_cast<float2*>(Cz + (long long)rlo * ldc + n0) = make_float2(c0, c1);
                *reinterpret_cast<float2*>(Cz + (long long)rhi * ldc + n0) = make_float2(c2, c3);
            } else {
                Cz[(long long)rlo * ldc + n0] = c0;
                Cz[(long long)rhi * ldc + n0] = c2;
                if (n0 + 1 < N) {
                    Cz[(long long)rlo * ldc + n0 + 1] = c1;
                    Cz[(long long)rhi * ldc + n0 + 1] = c3;
                }
            }
        }
    }
}

// ---------------------------------------------------------------------------
// Attention score: one warp per (b,a) pair.
//   score[b,a] = sum_k tanh(M[b*A+a, col_off+k] + hh[b,a]) * w[k] + d2db
// ---------------------------------------------------------------------------
__global__ __launch_bounds__(256)
void score_kernel(const float* __restrict__ Mv, const float* __restrict__ hh,
                  const float* __restrict__ w, const float* __restrict__ d2db,
                  float* __restrict__ score, int col_off)
{
    const int id   = blockIdx.x * 8 + (threadIdx.x >> 5);  // 0..BA_-1
    const int lane = threadIdx.x & 31;
    const float h  = hh[id];
    const float* row = Mv + (long long)id * KC_ + col_off;
    float s = 0.f;
    #pragma unroll 2
    for (int k = lane; k < A_; k += 32)
        s = fmaf(fast_tanh(row[k] + h), w[k], s);
    #pragma unroll
    for (int o = 16; o > 0; o >>= 1)
        s += __shfl_xor_sync(0xFFFFFFFFu, s, o);
    if (lane == 0) score[id] = s + d2db[0];
}

// softmax over A per batch row: ws[b,:] = softmax(score[b,:])
__global__ __launch_bounds__(256)
void softmax_kernel(const float* __restrict__ score, float* __restrict__ ws)
{
    const int b = blockIdx.x, tid = threadIdx.x;
    __shared__ float red[256];
    float v = (tid < A_) ? score[b * A_ + tid] : -INFINITY;
    red[tid] = v; __syncthreads();
    for (int s = 128; s > 0; s >>= 1) {
        if (tid < s) red[tid] = fmaxf(red[tid], red[tid + s]);
        __syncthreads();
    }
    const float mx = red[0]; __syncthreads();
    float e = (tid < A_) ? fast_expf(v - mx) : 0.f;
    red[tid] = e; __syncthreads();
    for (int s = 128; s > 0; s >>= 1) {
        if (tid < s) red[tid] += red[tid + s];
        __syncthreads();
    }
    if (tid < A_) ws[b * A_ + tid] = e / red[0];
}

// weighted att sum for TWO weight sets in one pass (res0, both layers)
__global__ __launch_bounds__(128)
void wsum2_kernel(const float* __restrict__ att, const float* __restrict__ ws,
                  float* __restrict__ outp)
{
    const int b = blockIdx.y;
    const int r = blockIdx.x * 128 + threadIdx.x;
    __shared__ float w0[A_], w1[A_];
    for (int a = threadIdx.x; a < A_; a += 128) {
        w0[a] = ws[b * A_ + a];
        w1[a] = ws[BA_ + b * A_ + a];
    }
    __syncthreads();
    const float* ab = att + (long long)b * A_ * R_ + r;
    float a0 = 0.f, a1 = 0.f;
    #pragma unroll 4
    for (int a = 0; a < A_; a++) {
        float v = ab[(long long)a * R_];
        a0 = fmaf(v, w0[a], a0);
        a1 = fmaf(v, w1[a], a1);
    }
    outp[b * R_ + r]           = a0;
    outp[B_ * R_ + b * R_ + r] = a1;
}

// single weighted att sum (+ addv)
__global__ __launch_bounds__(128)
void wsum_kernel(const float* __restrict__ att, const float* __restrict__ ws,
                 const float* __restrict__ addv, float* __restrict__ outp)
{
    const int b = blockIdx.y;
    const int r = blockIdx.x * 128 + threadIdx.x;
    __shared__ float w0[A_];
    for (int a = threadIdx.x; a < A_; a += 128)
        w0[a] = ws[b * A_ + a];
    __syncthreads();
    const float* ab = att + (long long)b * A_ * R_ + r;
    float a0 = 0.f;
    #pragma unroll 4
    for (int a = 0; a < A_; a++)
        a0 = fmaf(ab[(long long)a * R_], w0[a], a0);
    outp[b * R_ + r] = a0 + addv[b * R_ + r];
}

// ---------------------------------------------------------------------------
// Gates + cell update + mean over P
// ---------------------------------------------------------------------------
__global__ __launch_bounds__(256)
void gate_kernel(const float* __restrict__ sums,
                 const float* __restrict__ bi, const float* __restrict__ bh,
                 const float* __restrict__ ba,
                 const float* __restrict__ prev_c,
                 float* __restrict__ next_c, float* __restrict__ next_h)
{
    const int idx = blockIdx.x * 256 + threadIdx.x;
    const int b = idx >> 9, r = idx & (R_ - 1);
    const float pc = prev_c[idx];
    float ca = 0.f, ha = 0.f;
    #pragma unroll
    for (int p = 0; p < P_; p++) {
        const long long base = ((long long)p * B_ + b) * G4_;
        const int bb = p * G4_;
        float si = sums[base + r]        + bi[bb + r]        + bh[bb + r]        + ba[bb + r];
        float sf = sums[base + R_ + r]   + bi[bb + R_ + r]   + bh[bb + R_ + r]   + ba[bb + R_ + r];
        float so = sums[base + 2*R_ + r] + bi[bb + 2*R_ + r] + bh[bb + 2*R_ + r] + ba[bb + 2*R_ + r];
        float st = sums[base + 3*R_ + r] + bi[bb + 3*R_ + r] + bh[bb + 3*R_ + r] + ba[bb + 3*R_ + r];
        float ig = fast_sigmoid(si);
        float fg = fast_sigmoid(sf);
        float og = fast_sigmoid(so);
        float it = fast_tanh(st);
        float nc = fg * pc + ig * it;
        ca += nc;
        ha += og * fast_tanh(nc);
    }
    next_c[idx] = ca * (1.f / 3.f);
    next_h[idx] = ha * (1.f / 3.f);
}

__global__ __launch_bounds__(256)
void add_kernel(float* __restrict__ o, const float* __restrict__ a,
                const float* __restrict__ b)
{
    int i = blockIdx.x * 256 + threadIdx.x;
    o[i] = a[i] + b[i];
}

// ---------------------------------------------------------------------------
// In-place log-softmax over V per row
// ---------------------------------------------------------------------------
__global__ __launch_bounds__(256)
void logsoftmax_kernel(float* __restrict__ x)
{
    const int b = blockIdx.x, tid = threadIdx.x;
    __shared__ float red[256];
    float* row = x + (long long)b * V_;

    float mx = -INFINITY;
    for (int i = tid; i < V_; i += 256) mx = fmaxf(mx, row[i]);
    red[tid] = mx; __syncthreads();
    for (int s = 128; s > 0; s >>= 1) {
        if (tid < s) red[tid] = fmaxf(red[tid], red[tid + s]);
        __syncthreads();
    }
    mx = red[0]; __syncthreads();

    float sum = 0.f;
    for (int i = tid; i < V_; i += 256) sum += fast_expf(row[i] - mx);
    red[tid] = sum; __syncthreads();
    for (int s = 128; s > 0; s >>= 1) {
        if (tid < s) red[tid] += red[tid + s];
        __syncthreads();
    }
    const float lz = logf(red[0]) + mx;
    for (int i = tid; i < V_; i += 256) row[i] = row[i] - lz;
}

// ---------------------------------------------------------------------------
// Host launch
// ---------------------------------------------------------------------------
extern "C" void kernel_launch(void* const* d_in, const int* in_sizes, int n_in,
                              void* d_out, int out_size)
{
    (void)in_sizes; (void)n_in; (void)out_size;
    const float* x      = (const float*)d_in[0];
    const float* att    = (const float*)d_in[1];
    const float* inputs = (const float*)d_in[2];
    const float* i2h_w  = (const float*)d_in[3];
    const float* i2h_b  = (const float*)d_in[4];
    const float* h2h_w  = (const float*)d_in[5];
    const float* h2h_b  = (const float*)d_in[6];
    const float* a2h_w  = (const float*)d_in[7];
    const float* a2h_b  = (const float*)d_in[8];
    const float* a2a_w  = (const float*)d_in[9];
    const float* a2a_b  = (const float*)d_in[10];
    const float* h2a_w  = (const float*)d_in[11];
    const float* h2a_b  = (const float*)d_in[12];
    const float* d2d_w  = (const float*)d_in[13];
    const float* d2d_b  = (const float*)d_in[14];
    const float* proj_w = (const float*)d_in[15];
    const float* proj_b = (const float*)d_in[16];
    float* out = (float*)d_out;

    float *pM, *phh2, *phh, *pscore, *pws, *patt0, *psums, *pxt, *pnh;
    cudaGetSymbolAddress((void**)&pM,     gM);
    cudaGetSymbolAddress((void**)&phh2,   g_hh2);
    cudaGetSymbolAddress((void**)&phh,    g_hh);
    cudaGetSymbolAddress((void**)&pscore, g_score);
    cudaGetSymbolAddress((void**)&pws,    g_ws);
    cudaGetSymbolAddress((void**)&patt0,  g_att0);
    cudaGetSymbolAddress((void**)&psums,  g_sums);
    cudaGetSymbolAddress((void**)&pxt,    g_xt);
    cudaGetSymbolAddress((void**)&pnh,    g_nh);

    static bool attr_done = false;
    const int smem128 = 3 * (128 + 128) * 32 * 4;  // 98304
    const int smem64  = 3 * (128 + 64)  * 32 * 4;  // 73728
    if (!attr_done) {
        cudaFuncSetAttribute(gemm_mma<128>, cudaFuncAttributeMaxDynamicSharedMemorySize, smem128);
        cudaFuncSetAttribute(gemm_mma<64>,  cudaFuncAttributeMaxDynamicSharedMemorySize, smem64);
        attr_done = true;
    }

    dim3 blk(256);
    const size_t wst = (size_t)G4_ * R_;

    // 1) Big logits GEMM: gM = att @ a2a_w^T + a2a_b   (50176 x 784 x 512)
    gemm_mma<128><<<dim3(7, BA_ / 128, 1), blk, smem128>>>(
        att, att, att, a2a_w, a2a_w, a2a_w, pM, a2a_b,
        KC_, R_, KC_, 0, 0, 0, 0);

    // 2) hh for call0 of both layers (batched z=layer; prev_h from inputs)
    {
        const float* ph = inputs + (size_t)B_ * R_;
        gemm_mma<64><<<dim3(4, 2, 2), blk, smem64>>>(
            ph, ph, ph, h2a_w, h2a_w, h2a_w, phh2, h2a_b,
            A_, R_, A_,
            (long long)2 * B_ * R_, (long long)2 * A_ * R_,
            (long long)B_ * A_, (long long)2 * A_);
    }

    // 3) scores + softmax + weighted sums for call0 of both layers
    for (int lyr = 0; lyr < 2; lyr++) {
        const int call = lyr * 2;
        score_kernel<<<BA_ / 8, blk>>>(pM, phh2 + (size_t)lyr * BA_,
                                       d2d_w + (size_t)call * A_, d2d_b + call,
                                       pscore + (size_t)lyr * BA_, call * A_);
        softmax_kernel<<<B_, blk>>>(pscore + (size_t)lyr * BA_, pws + (size_t)lyr * BA_);
    }
    wsum2_kernel<<<dim3(R_ / 128, B_), dim3(128)>>>(att, pws, patt0);

    for (int i = 0; i < L_; i++) {
        const float* prev_c = inputs + (size_t)(2 * i) * B_ * R_;
        const float* prev_h = inputs + (size_t)(2 * i + 1) * B_ * R_;

        const float* xt = x;
        if (i == 1) {
            add_kernel<<<(B_ * R_) / 256, blk>>>(pxt, x, out + (size_t)1 * B_ * R_);
            xt = pxt;
        }

        // fused gate GEMM: K=1536, A segments [xt, prev_h, att0_i], B segments
        // [i2h_w, h2h_w, a2h_w] for this layer, batched over p.
        gemm_mma<64><<<dim3(32, 2, P_), blk, smem64>>>(
            xt, prev_h, patt0 + (size_t)i * B_ * R_,
            i2h_w + (size_t)i * P_ * wst,
            h2h_w + (size_t)i * P_ * wst,
            a2h_w + (size_t)i * P_ * wst,
            psums, nullptr,
            G4_, 3 * R_, G4_,
            0, (long long)wst, (long long)B_ * G4_, 0);

        gate_kernel<<<(B_ * R_) / 256, blk>>>(
            psums,
            i2h_b + (size_t)i * P_ * G4_,
            h2h_b + (size_t)i * P_ * G4_,
            a2h_b + (size_t)i * P_ * G4_,
            prev_c,
            out + (size_t)(2 * i) * B_ * R_, pnh);

        // call1 attention on next_h
        const int c1 = 2 * i + 1;
        {
            const float* bw = h2a_w + (size_t)c1 * A_ * R_;
            gemm_mma<64><<<dim3(4, 2, 1), blk, smem64>>>(
                pnh, pnh, pnh, bw, bw, bw, phh, h2a_b + (size_t)c1 * A_,
                A_, R_, A_, 0, 0, 0, 0);
        }
        score_kernel<<<BA_ / 8, blk>>>(pM, phh, d2d_w + (size_t)c1 * A_,
                                       d2d_b + c1, pscore, c1 * A_);
        softmax_kernel<<<B_, blk>>>(pscore, pws);
        wsum_kernel<<<dim3(R_ / 128, B_), dim3(128)>>>(
            att, pws, pnh, out + (size_t)(2 * i + 1) * B_ * R_);
    }

    // projection + log-softmax
    gemm_mma<64><<<dim3((V_ + 63) / 64, 2, 1), blk, smem64>>>(
        out + (size_t)3 * B_ * R_, out, out,
        proj_w, proj_w, proj_w,
        out + (size_t)4 * B_ * R_, proj_b,
        V_, R_, V_, 0, 0, 0, 0);
    logsoftmax_kernel<<<B_, blk>>>(out + (size_t)4 * B_ * R_);
}